// round 1
// baseline (speedup 1.0000x reference)
#include <cuda_runtime.h>
#include <math.h>

#define BATCH  128
#define NOSC   1024
#define STEPS  10
#define DT     0.1f
#define NSPLIT 4
#define BN     (BATCH * NOSC)

#define TI 64      // i-tile (oscillator outputs per block)
#define TB 64      // batch-tile per block
#define JT 32      // inner j tile
#define JCHUNK (NOSC / NSPLIT)   // 256 j per split

// Persistent state (no device allocation allowed)
__device__ float g_theta[BN];
__device__ float g_sin[BN];
__device__ float g_cos[BN];
__device__ float g_pS[NSPLIT * BN];
__device__ float g_pC[NSPLIT * BN];

__global__ void init_kernel(const float* __restrict__ theta_init) {
    int idx = blockIdx.x * blockDim.x + threadIdx.x;
    if (idx < BN) {
        float t = theta_init[idx];
        g_theta[idx] = t;
        g_sin[idx]   = sinf(t);
        g_cos[idx]   = cosf(t);
    }
}

// Computes partial  S[b,i] = sum_j K[i,j]*sin(theta[b,j]),  C likewise,
// for j in this block's split chunk.  Grid: (BATCH/TB, NOSC/TI, NSPLIT), 256 thr.
__global__ __launch_bounds__(256, 1) void step_gemm(const float* __restrict__ K) {
    __shared__ float sK[JT][TI + 4];
    __shared__ float sS[JT][TB + 4];
    __shared__ float sC[JT][TB + 4];

    const int tid    = threadIdx.x;
    const int bblk   = blockIdx.x * TB;
    const int iblk   = blockIdx.y * TI;
    const int split  = blockIdx.z;
    const int j0base = split * JCHUNK;
    const int tx = tid & 15;   // -> 4 i's
    const int ty = tid >> 4;   // -> 4 b's

    float aS[4][4], aC[4][4];
#pragma unroll
    for (int b = 0; b < 4; b++)
#pragma unroll
        for (int i = 0; i < 4; i++) { aS[b][i] = 0.f; aC[b][i] = 0.f; }

    for (int jt = 0; jt < JCHUNK; jt += JT) {
        const int j0 = j0base + jt;
        // Cooperative loads: 64 rows x 32 cols per tile, transposed into smem.
#pragma unroll
        for (int v = 0; v < 2; v++) {
            int e  = tid + v * 256;        // 0..511
            int r  = e >> 3;               // row 0..63
            int jj = (e & 7) * 4;          // col group
            float4 kv = *reinterpret_cast<const float4*>(
                &K[(size_t)(iblk + r) * NOSC + j0 + jj]);
            sK[jj + 0][r] = kv.x; sK[jj + 1][r] = kv.y;
            sK[jj + 2][r] = kv.z; sK[jj + 3][r] = kv.w;
            float4 sv = *reinterpret_cast<const float4*>(
                &g_sin[(size_t)(bblk + r) * NOSC + j0 + jj]);
            sS[jj + 0][r] = sv.x; sS[jj + 1][r] = sv.y;
            sS[jj + 2][r] = sv.z; sS[jj + 3][r] = sv.w;
            float4 cv = *reinterpret_cast<const float4*>(
                &g_cos[(size_t)(bblk + r) * NOSC + j0 + jj]);
            sC[jj + 0][r] = cv.x; sC[jj + 1][r] = cv.y;
            sC[jj + 2][r] = cv.z; sC[jj + 3][r] = cv.w;
        }
        __syncthreads();

#pragma unroll
        for (int j = 0; j < JT; j++) {
            float4 kv = *reinterpret_cast<const float4*>(&sK[j][tx * 4]);
            float4 sv = *reinterpret_cast<const float4*>(&sS[j][ty * 4]);
            float4 cv = *reinterpret_cast<const float4*>(&sC[j][ty * 4]);
            float kk[4] = {kv.x, kv.y, kv.z, kv.w};
            float ss[4] = {sv.x, sv.y, sv.z, sv.w};
            float cc[4] = {cv.x, cv.y, cv.z, cv.w};
#pragma unroll
            for (int b = 0; b < 4; b++)
#pragma unroll
                for (int i = 0; i < 4; i++) {
                    aS[b][i] = fmaf(kk[i], ss[b], aS[b][i]);
                    aC[b][i] = fmaf(kk[i], cc[b], aC[b][i]);
                }
        }
        __syncthreads();
    }

    const size_t base = (size_t)split * BN;
#pragma unroll
    for (int b = 0; b < 4; b++) {
        int brow = bblk + ty * 4 + b;
        size_t off = base + (size_t)brow * NOSC + iblk + tx * 4;
        float4 vs = {aS[b][0], aS[b][1], aS[b][2], aS[b][3]};
        float4 vc = {aC[b][0], aC[b][1], aC[b][2], aC[b][3]};
        *reinterpret_cast<float4*>(&g_pS[off]) = vs;
        *reinterpret_cast<float4*>(&g_pC[off]) = vc;
    }
}

__global__ void step_update(const float* __restrict__ omega,
                            const float* __restrict__ kglobal) {
    int idx = blockIdx.x * blockDim.x + threadIdx.x;
    if (idx >= BN) return;
    int i = idx & (NOSC - 1);
    float S = g_pS[idx] + g_pS[BN + idx] + g_pS[2 * BN + idx] + g_pS[3 * BN + idx];
    float C = g_pC[idx] + g_pC[BN + idx] + g_pC[2 * BN + idx] + g_pC[3 * BN + idx];
    float s = g_sin[idx], c = g_cos[idx];
    float coupling = c * S - s * C;
    float scale = kglobal[0] * (1.0f / NOSC);
    float t = g_theta[idx] + DT * (omega[i] + scale * coupling);
    float sn = sinf(t), cn = cosf(t);
    g_theta[idx] = atan2f(sn, cn);   // wrap to (-pi, pi], same as reference
    g_sin[idx] = sn;
    g_cos[idx] = cn;
}

__global__ void finalize_kernel(float* __restrict__ out) {
    __shared__ float rs[256], rc[256];
    const int b = blockIdx.x, tid = threadIdx.x;
    float ss = 0.f, cs = 0.f;
    for (int j = tid; j < NOSC; j += 256) {
        int idx = b * NOSC + j;
        out[idx] = g_theta[idx];
        ss += g_sin[idx];
        cs += g_cos[idx];
    }
    rs[tid] = ss; rc[tid] = cs;
    __syncthreads();
    for (int off = 128; off > 0; off >>= 1) {
        if (tid < off) { rs[tid] += rs[tid + off]; rc[tid] += rc[tid + off]; }
        __syncthreads();
    }
    if (tid == 0) {
        float sm = rs[0] * (1.0f / NOSC);
        float cm = rc[0] * (1.0f / NOSC);
        out[BN + b] = sqrtf(cm * cm + sm * sm);
    }
}

extern "C" void kernel_launch(void* const* d_in, const int* in_sizes, int n_in,
                              void* d_out, int out_size) {
    const float* theta_init = (const float*)d_in[0];
    const float* K          = (const float*)d_in[1];
    const float* omega      = (const float*)d_in[2];
    const float* kglobal    = (const float*)d_in[3];
    float* out = (float*)d_out;

    init_kernel<<<BN / 256, 256>>>(theta_init);
    dim3 g(BATCH / TB, NOSC / TI, NSPLIT);   // (2, 16, 4) = 128 blocks
    for (int s = 0; s < STEPS; s++) {
        step_gemm<<<g, 256>>>(K);
        step_update<<<BN / 256, 256>>>(omega, kglobal);
    }
    finalize_kernel<<<BATCH, 256>>>(out);
}

// round 3
// speedup vs baseline: 1.3579x; 1.3579x over previous
#include <cuda_runtime.h>
#include <cuda_bf16.h>
#include <math.h>
#include <stdint.h>

#define BATCH 128
#define NOSC  1024
#define STEPS 10
#define DT    0.1f
#define BN    (BATCH*NOSC)

#define TM 32                 // batch rows per CTA
#define TN 64                 // osc cols per CTA
#define KS 64                 // k elements per pipeline stage
#define NSTAGE (NOSC/KS)      // 16
#define LDA 72                // smem row stride (bf16 elems): 144B, conflict-free

// ---------------- persistent device state (no allocation allowed) -------------
__device__ float          g_theta[BN];
__device__ __nv_bfloat16  g_sinb[2][BN];   // double-buffered (cross-CTA race fix)
__device__ __nv_bfloat16  g_cosb[2][BN];
__device__ __nv_bfloat16  g_Kb[NOSC*NOSC];

// ---------------- helpers -----------------------------------------------------
__device__ __forceinline__ uint32_t s2u(const void* p) {
    return (uint32_t)__cvta_generic_to_shared(p);
}
__device__ __forceinline__ void cp16(void* dst, const void* src) {
    asm volatile("cp.async.cg.shared.global [%0], [%1], 16;"
                 :: "r"(s2u(dst)), "l"(src) : "memory");
}
__device__ __forceinline__ void ldsm4(uint32_t& r0, uint32_t& r1, uint32_t& r2,
                                      uint32_t& r3, const void* p) {
    asm volatile("ldmatrix.sync.aligned.m8n8.x4.shared.b16 {%0,%1,%2,%3}, [%4];"
                 : "=r"(r0), "=r"(r1), "=r"(r2), "=r"(r3) : "r"(s2u(p)));
}
__device__ __forceinline__ void mma16816(float* d, const uint32_t* a,
                                         uint32_t b0, uint32_t b1) {
    asm volatile(
        "mma.sync.aligned.m16n8k16.row.col.f32.bf16.bf16.f32 "
        "{%0,%1,%2,%3}, {%4,%5,%6,%7}, {%8,%9}, {%0,%1,%2,%3};"
        : "+f"(d[0]), "+f"(d[1]), "+f"(d[2]), "+f"(d[3])
        : "r"(a[0]), "r"(a[1]), "r"(a[2]), "r"(a[3]), "r"(b0), "r"(b1));
}

// ---------------- init: theta/sin/cos(buf 0) + K -> bf16 ----------------------
__global__ void init_kernel(const float* __restrict__ theta_init,
                            const float* __restrict__ K) {
    int idx = blockIdx.x * blockDim.x + threadIdx.x;   // 0 .. NOSC*NOSC-1
    g_Kb[idx] = __float2bfloat16(K[idx]);
    if (idx < BN) {
        float t = theta_init[idx];
        g_theta[idx]   = t;
        g_sinb[0][idx] = __float2bfloat16(sinf(t));
        g_cosb[0][idx] = __float2bfloat16(cosf(t));
    }
}

// ---------------- fused step: 2 bf16 GEMMs (mma.sync) + phase update ----------
__global__ __launch_bounds__(256, 1) void step_kernel(const float* __restrict__ omega,
                                                      const float* __restrict__ kg,
                                                      int rb) {
    __shared__ __nv_bfloat16 sAs[2][TM][LDA];
    __shared__ __nv_bfloat16 sAc[2][TM][LDA];
    __shared__ __nv_bfloat16 sB [2][TN][LDA];

    const int tid  = threadIdx.x;
    const int lane = tid & 31;
    const int wid  = tid >> 5;
    const int n0   = blockIdx.x * TN;     // 16 n-tiles
    const int m0   = blockIdx.y * TM;     // 4 m-tiles
    const int wy   = wid & 1;             // M: 2 x 16
    const int wx   = wid >> 1;            // N: 4 x 16
    const int wbuf = rb ^ 1;

    const __nv_bfloat16* sin_r = g_sinb[rb];
    const __nv_bfloat16* cos_r = g_cosb[rb];

    auto load_stage = [&](int s) {
        int buf = s & 1, k0 = s * KS;
#pragma unroll
        for (int v = 0; v < 4; v++) {
            int e = tid + v * 256;
            if (e < 256) {
                int r = e >> 3, c = e & 7;
                cp16(&sAs[buf][r][c * 8], sin_r + (size_t)(m0 + r) * NOSC + k0 + c * 8);
            } else if (e < 512) {
                int e2 = e - 256, r = e2 >> 3, c = e2 & 7;
                cp16(&sAc[buf][r][c * 8], cos_r + (size_t)(m0 + r) * NOSC + k0 + c * 8);
            } else {
                int e2 = e - 512, r = e2 >> 3, c = e2 & 7;
                cp16(&sB[buf][r][c * 8], g_Kb + (size_t)(n0 + r) * NOSC + k0 + c * 8);
            }
        }
        asm volatile("cp.async.commit_group;" ::: "memory");
    };

    float aS[2][4] = {}, aC[2][4] = {};

    load_stage(0);
#pragma unroll 1
    for (int s = 0; s < NSTAGE; s++) {
        if (s + 1 < NSTAGE) {
            load_stage(s + 1);
            asm volatile("cp.async.wait_group 1;" ::: "memory");
        } else {
            asm volatile("cp.async.wait_group 0;" ::: "memory");
        }
        __syncthreads();
        const int buf = s & 1;
        const int ar = wy * 16 + ((lane >> 3) & 1) * 8 + (lane & 7);
        const int br = wx * 16 + ((lane >> 4) << 3) + (lane & 7);
#pragma unroll
        for (int kk = 0; kk < 4; kk++) {
            const int k0 = kk * 16;
            const int ac = k0 + (lane >> 4) * 8;
            const int bc = k0 + ((lane >> 3) & 1) * 8;
            uint32_t sa[4], ca[4], bb[4];
            ldsm4(sa[0], sa[1], sa[2], sa[3], &sAs[buf][ar][ac]);
            ldsm4(ca[0], ca[1], ca[2], ca[3], &sAc[buf][ar][ac]);
            ldsm4(bb[0], bb[1], bb[2], bb[3], &sB[buf][br][bc]);
            mma16816(aS[0], sa, bb[0], bb[1]);
            mma16816(aS[1], sa, bb[2], bb[3]);
            mma16816(aC[0], ca, bb[0], bb[1]);
            mma16816(aC[1], ca, bb[2], bb[3]);
        }
        __syncthreads();
    }

    // ---- fused epilogue: Kuramoto phase update, wrap deferred to finalize ----
    const float scale = kg[0] * (1.0f / NOSC);
    const int g = lane >> 2, tig = lane & 3;
#pragma unroll
    for (int half = 0; half < 2; half++) {
#pragma unroll
        for (int ns = 0; ns < 2; ns++) {
#pragma unroll
            for (int cc = 0; cc < 2; cc++) {
                int m   = m0 + wy * 16 + half * 8 + g;
                int osc = n0 + wx * 16 + ns * 8 + tig * 2 + cc;
                int idx = m * NOSC + osc;
                float S  = aS[ns][half * 2 + cc];
                float C  = aC[ns][half * 2 + cc];
                float so = __bfloat162float(sin_r[idx]);
                float co = __bfloat162float(cos_r[idx]);
                float t2 = g_theta[idx] + DT * (omega[osc] + scale * (co * S - so * C));
                float sn, cn;
                __sincosf(t2, &sn, &cn);
                g_theta[idx]      = t2;   // unwrapped; wrap is 2*pi-invariant for trig
                g_sinb[wbuf][idx] = __float2bfloat16(sn);
                g_cosb[wbuf][idx] = __float2bfloat16(cn);
            }
        }
    }
}

// ---------------- finalize: wrap + coherence (accurate fp32) ------------------
__global__ void finalize_kernel(float* __restrict__ out) {
    __shared__ float rs[256], rc[256];
    const int b = blockIdx.x, tid = threadIdx.x;
    float ss = 0.f, cs = 0.f;
    for (int j = tid; j < NOSC; j += 256) {
        int idx = b * NOSC + j;
        float t = g_theta[idx];
        float sn = sinf(t), cn = cosf(t);
        out[idx] = atan2f(sn, cn);        // wrap to (-pi, pi], matches reference
        ss += sn; cs += cn;
    }
    rs[tid] = ss; rc[tid] = cs;
    __syncthreads();
    for (int off = 128; off > 0; off >>= 1) {
        if (tid < off) { rs[tid] += rs[tid + off]; rc[tid] += rc[tid + off]; }
        __syncthreads();
    }
    if (tid == 0) {
        float sm = rs[0] * (1.0f / NOSC);
        float cm = rc[0] * (1.0f / NOSC);
        out[BN + b] = sqrtf(cm * cm + sm * sm);
    }
}

extern "C" void kernel_launch(void* const* d_in, const int* in_sizes, int n_in,
                              void* d_out, int out_size) {
    const float* theta_init = (const float*)d_in[0];
    const float* K          = (const float*)d_in[1];
    const float* omega      = (const float*)d_in[2];
    const float* kglobal    = (const float*)d_in[3];
    float* out = (float*)d_out;

    init_kernel<<<(NOSC * NOSC) / 256, 256>>>(theta_init, K);
    dim3 grid(NOSC / TN, BATCH / TM);     // (16, 4) = 64 CTAs
    for (int s = 0; s < STEPS; s++)
        step_kernel<<<grid, 256>>>(omega, kglobal, s & 1);
    finalize_kernel<<<BATCH, 256>>>(out);
}

// round 4
// speedup vs baseline: 1.9363x; 1.4260x over previous
#include <cuda_runtime.h>
#include <cuda_bf16.h>
#include <math.h>
#include <stdint.h>

#define BATCH 128
#define NOSC  1024
#define STEPS 10
#define DT    0.1f
#define BN    (BATCH*NOSC)

#define TM 32                 // batch rows per CTA
#define TN 32                 // osc cols per CTA
#define KS 64                 // k elements per pipeline stage
#define NSTAGE (NOSC/KS)      // 16
#define LDA 72                // smem row stride (bf16): 144B, ldmatrix conflict-free
#define TILE_E (32*LDA)       // 2304 bf16 elems per 32-row tile
#define STG_E  (3*TILE_E)     // sin + cos + B per stage
#define SMEM_BYTES (4*STG_E*2)  // 4-stage ring = 55296 B

// ---------------- persistent device state (no allocation allowed) -------------
__device__ float          g_theta[BN];
__device__ __nv_bfloat16  g_sinb[2][BN];   // double-buffered (cross-CTA race fix)
__device__ __nv_bfloat16  g_cosb[2][BN];
__device__ __nv_bfloat16  g_Kb[NOSC*NOSC];

// ---------------- helpers -----------------------------------------------------
__device__ __forceinline__ uint32_t s2u(const void* p) {
    return (uint32_t)__cvta_generic_to_shared(p);
}
__device__ __forceinline__ void cp16(void* dst, const void* src) {
    asm volatile("cp.async.cg.shared.global [%0], [%1], 16;"
                 :: "r"(s2u(dst)), "l"(src) : "memory");
}
__device__ __forceinline__ void ldsm4(uint32_t& r0, uint32_t& r1, uint32_t& r2,
                                      uint32_t& r3, const void* p) {
    asm volatile("ldmatrix.sync.aligned.m8n8.x4.shared.b16 {%0,%1,%2,%3}, [%4];"
                 : "=r"(r0), "=r"(r1), "=r"(r2), "=r"(r3) : "r"(s2u(p)));
}
__device__ __forceinline__ void ldsm2(uint32_t& r0, uint32_t& r1, const void* p) {
    asm volatile("ldmatrix.sync.aligned.m8n8.x2.shared.b16 {%0,%1}, [%2];"
                 : "=r"(r0), "=r"(r1) : "r"(s2u(p)));
}
__device__ __forceinline__ void mma16816(float* d, const uint32_t* a,
                                         uint32_t b0, uint32_t b1) {
    asm volatile(
        "mma.sync.aligned.m16n8k16.row.col.f32.bf16.bf16.f32 "
        "{%0,%1,%2,%3}, {%4,%5,%6,%7}, {%8,%9}, {%0,%1,%2,%3};"
        : "+f"(d[0]), "+f"(d[1]), "+f"(d[2]), "+f"(d[3])
        : "r"(a[0]), "r"(a[1]), "r"(a[2]), "r"(a[3]), "r"(b0), "r"(b1));
}

// ---------------- init: theta/sin/cos(buf 0) + K -> bf16 ----------------------
__global__ void init_kernel(const float* __restrict__ theta_init,
                            const float* __restrict__ K) {
    int idx = blockIdx.x * blockDim.x + threadIdx.x;   // 0 .. NOSC*NOSC-1
    g_Kb[idx] = __float2bfloat16(K[idx]);
    if (idx < BN) {
        float t = theta_init[idx];
        g_theta[idx]   = t;
        g_sinb[0][idx] = __float2bfloat16(sinf(t));
        g_cosb[0][idx] = __float2bfloat16(cosf(t));
    }
}

// ---------------- fused step: 2 bf16 GEMMs (mma.sync) + phase update ----------
__global__ __launch_bounds__(256, 1) void step_kernel(const float* __restrict__ omega,
                                                      const float* __restrict__ kg,
                                                      int rb) {
    extern __shared__ __nv_bfloat16 sm[];   // 4 stages x (sin|cos|B) x 32x72

    const int tid  = threadIdx.x;
    const int lane = tid & 31;
    const int wid  = tid >> 5;
    const int n0   = blockIdx.x * TN;     // 32 n-tiles
    const int m0   = blockIdx.y * TM;     // 4 m-tiles
    const int wy   = wid & 1;             // M: 2 x m16
    const int wn   = wid >> 1;            // N: 4 x n8
    const int wbuf = rb ^ 1;

    const __nv_bfloat16* sin_r = g_sinb[rb];
    const __nv_bfloat16* cos_r = g_cosb[rb];

    const int lr = tid >> 3;              // 0..31
    const int lc = (tid & 7) * 8;         // 0..56

    auto load_stage = [&](int s) {
        __nv_bfloat16* st = sm + (s & 3) * STG_E;
        const int k0 = s * KS;
        cp16(st + lr * LDA + lc,              sin_r + (size_t)(m0 + lr) * NOSC + k0 + lc);
        cp16(st + TILE_E + lr * LDA + lc,     cos_r + (size_t)(m0 + lr) * NOSC + k0 + lc);
        cp16(st + 2 * TILE_E + lr * LDA + lc, g_Kb  + (size_t)(n0 + lr) * NOSC + k0 + lc);
        asm volatile("cp.async.commit_group;" ::: "memory");
    };

    float aS[4] = {}, aC[4] = {};

    load_stage(0);
    load_stage(1);

    const int ar  = wy * 16 + ((lane >> 3) & 1) * 8 + (lane & 7);
    const int l15 = lane & 15;
    const int br  = wn * 8 + (l15 & 7);
    const int bkh = ((l15 >> 3) & 1) * 8;

#pragma unroll 1
    for (int s = 0; s < NSTAGE; s++) {
        if (s + 2 < NSTAGE) {
            load_stage(s + 2);
            asm volatile("cp.async.wait_group 2;" ::: "memory");
        } else if (s + 1 < NSTAGE) {
            asm volatile("cp.async.wait_group 1;" ::: "memory");
        } else {
            asm volatile("cp.async.wait_group 0;" ::: "memory");
        }
        __syncthreads();   // single barrier per stage (4-buffer ring, skew-safe)

        const __nv_bfloat16* st = sm + (s & 3) * STG_E;
#pragma unroll
        for (int kk = 0; kk < 4; kk++) {
            const int k0 = kk * 16;
            const int ac = k0 + (lane >> 4) * 8;
            uint32_t sa[4], ca[4], b0, b1;
            ldsm4(sa[0], sa[1], sa[2], sa[3], st + ar * LDA + ac);
            ldsm4(ca[0], ca[1], ca[2], ca[3], st + TILE_E + ar * LDA + ac);
            ldsm2(b0, b1, st + 2 * TILE_E + br * LDA + k0 + bkh);
            mma16816(aS, sa, b0, b1);
            mma16816(aC, ca, b0, b1);
        }
    }

    // ---- fused epilogue: Kuramoto phase update, wrap deferred to finalize ----
    const float scale = kg[0] * (1.0f / NOSC);
    const int g = lane >> 2, tig = lane & 3;
#pragma unroll
    for (int half = 0; half < 2; half++) {
        int m = m0 + wy * 16 + half * 8 + g;
#pragma unroll
        for (int cc = 0; cc < 2; cc++) {
            int osc = n0 + wn * 8 + tig * 2 + cc;
            int idx = m * NOSC + osc;
            float S  = aS[half * 2 + cc];
            float C  = aC[half * 2 + cc];
            float so = __bfloat162float(sin_r[idx]);
            float co = __bfloat162float(cos_r[idx]);
            float t2 = g_theta[idx] + DT * (omega[osc] + scale * (co * S - so * C));
            float sn, cn;
            __sincosf(t2, &sn, &cn);
            g_theta[idx]      = t2;   // unwrapped; wrap is 2*pi-invariant for trig
            g_sinb[wbuf][idx] = __float2bfloat16(sn);
            g_cosb[wbuf][idx] = __float2bfloat16(cn);
        }
    }
}

// ---------------- finalize: wrap + coherence (accurate fp32) ------------------
__global__ void finalize_kernel(float* __restrict__ out) {
    __shared__ float rs[256], rc[256];
    const int b = blockIdx.x, tid = threadIdx.x;
    float ss = 0.f, cs = 0.f;
    for (int j = tid; j < NOSC; j += 256) {
        int idx = b * NOSC + j;
        float t = g_theta[idx];
        float sn = sinf(t), cn = cosf(t);
        out[idx] = atan2f(sn, cn);        // wrap to (-pi, pi], matches reference
        ss += sn; cs += cn;
    }
    rs[tid] = ss; rc[tid] = cs;
    __syncthreads();
    for (int off = 128; off > 0; off >>= 1) {
        if (tid < off) { rs[tid] += rs[tid + off]; rc[tid] += rc[tid + off]; }
        __syncthreads();
    }
    if (tid == 0) {
        float sm2 = rs[0] * (1.0f / NOSC);
        float cm  = rc[0] * (1.0f / NOSC);
        out[BN + b] = sqrtf(cm * cm + sm2 * sm2);
    }
}

extern "C" void kernel_launch(void* const* d_in, const int* in_sizes, int n_in,
                              void* d_out, int out_size) {
    const float* theta_init = (const float*)d_in[0];
    const float* K          = (const float*)d_in[1];
    const float* omega      = (const float*)d_in[2];
    const float* kglobal    = (const float*)d_in[3];
    float* out = (float*)d_out;

    cudaFuncSetAttribute(step_kernel, cudaFuncAttributeMaxDynamicSharedMemorySize,
                         SMEM_BYTES);

    init_kernel<<<(NOSC * NOSC) / 256, 256>>>(theta_init, K);
    dim3 grid(NOSC / TN, BATCH / TM);     // (32, 4) = 128 CTAs
    for (int s = 0; s < STEPS; s++)
        step_kernel<<<grid, 256, SMEM_BYTES>>>(omega, kglobal, s & 1);
    finalize_kernel<<<BATCH, 256>>>(out);
}